// round 2
// baseline (speedup 1.0000x reference)
#include <cuda_runtime.h>

// Problem constants
namespace {
constexpr int kB  = 2;
constexpr int kS  = 2048;
constexpr int kD  = 1024;
constexpr int kH  = 16;
constexpr int kDK = 64;
constexpr int kBH = kB * kH;        // 32
constexpr int kBS = kB * kS;        // 4096
constexpr int kNRows = kBH * kS;    // 65536 softmax rows
}

// Scratch (allocation-free rule: __device__ globals)
__device__ float g_q [kBH * kS * kDK];   // 16 MB
__device__ float g_kr[kBH * kS * kDK];   // 16 MB  (k_proj + r_proj)
__device__ float g_v [kBH * kS * kDK];   // 16 MB
__device__ float g_rmax[kNRows];
__device__ float g_rinv[kNRows];

// ---------------------------------------------------------------------------
// Projection GEMM:  Y[m,e] = sum_d X1[m,d]*W1[e,d] (+ X2[m,d]*W2[e,d]) + bias
// written to head-major layout (b,h,s,dk).  dst_sel: 0=q, 1=kr, 2=v
// 128x128 tile, BK=8, 256 threads, 8x8 per-thread microtile.
// ---------------------------------------------------------------------------
__global__ __launch_bounds__(256) void proj_kernel(
    const float* __restrict__ X1, const float* __restrict__ W1, const float* __restrict__ bias1,
    const float* __restrict__ X2, const float* __restrict__ W2, const float* __restrict__ bias2,
    int dst_sel)
{
    __shared__ float As[8][128];
    __shared__ float Bs[8][128];

    const int m0  = blockIdx.y * 128;   // rows in (B*S)
    const int n0  = blockIdx.x * 128;   // cols in E=D
    const int tid = threadIdx.x;
    const int tx  = tid & 15;
    const int ty  = tid >> 4;
    const int lr  = tid >> 1;           // 0..127  (tile row for loads)
    const int lc  = (tid & 1) * 4;      // 0 or 4  (k sub-offset)

    float acc[8][8];
#pragma unroll
    for (int i = 0; i < 8; ++i)
#pragma unroll
        for (int j = 0; j < 8; ++j) acc[i][j] = 0.f;

    for (int pass = 0; pass < 2; ++pass) {
        const float* X = (pass == 0) ? X1 : X2;
        const float* W = (pass == 0) ? W1 : W2;
        if (X == nullptr) break;
        for (int k0 = 0; k0 < kD; k0 += 8) {
            float4 av = *reinterpret_cast<const float4*>(&X[(m0 + lr) * kD + k0 + lc]);
            float4 bv = *reinterpret_cast<const float4*>(&W[(n0 + lr) * kD + k0 + lc]);
            __syncthreads();
            As[lc + 0][lr] = av.x; As[lc + 1][lr] = av.y;
            As[lc + 2][lr] = av.z; As[lc + 3][lr] = av.w;
            Bs[lc + 0][lr] = bv.x; Bs[lc + 1][lr] = bv.y;
            Bs[lc + 2][lr] = bv.z; Bs[lc + 3][lr] = bv.w;
            __syncthreads();
#pragma unroll
            for (int kk = 0; kk < 8; ++kk) {
                float4 a0 = *reinterpret_cast<const float4*>(&As[kk][ty * 8]);
                float4 a1 = *reinterpret_cast<const float4*>(&As[kk][ty * 8 + 4]);
                float4 b0 = *reinterpret_cast<const float4*>(&Bs[kk][tx * 8]);
                float4 b1 = *reinterpret_cast<const float4*>(&Bs[kk][tx * 8 + 4]);
                float a[8] = {a0.x, a0.y, a0.z, a0.w, a1.x, a1.y, a1.z, a1.w};
                float b[8] = {b0.x, b0.y, b0.z, b0.w, b1.x, b1.y, b1.z, b1.w};
#pragma unroll
                for (int i = 0; i < 8; ++i)
#pragma unroll
                    for (int j = 0; j < 8; ++j) acc[i][j] += a[i] * b[j];
            }
        }
    }

    float* __restrict__ dst = (dst_sel == 0) ? g_q : (dst_sel == 1) ? g_kr : g_v;

    // bias for this thread's 8 output columns (hoisted out of row loop)
    float bsum[8];
#pragma unroll
    for (int j = 0; j < 8; ++j) {
        const int e = n0 + tx * 8 + j;
        bsum[j] = bias1[e] + (X2 ? bias2[e] : 0.f);
    }

#pragma unroll
    for (int i = 0; i < 8; ++i) {
        const int m    = m0 + ty * 8 + i;
        const int bidx = m >> 11;          // m / kS
        const int s    = m & (kS - 1);
#pragma unroll
        for (int j = 0; j < 8; ++j) {
            const int e  = n0 + tx * 8 + j;
            const int h  = e >> 6;         // e / kDK
            const int dk = e & 63;
            dst[((bidx * kH + h) * kS + s) * kDK + dk] = acc[i][j] + bsum[j];
        }
    }
}

// ---------------------------------------------------------------------------
// Scores: S = q @ kr^T * scale, masked; raw scores written into p region.
// grid (S/128, S/128, BH)
// ---------------------------------------------------------------------------
__global__ __launch_bounds__(256) void scores_kernel(const int* __restrict__ mask,
                                                     float* __restrict__ p)
{
    __shared__ float As[8][128];
    __shared__ float Bs[8][128];

    const int bh  = blockIdx.z;
    const int m0  = blockIdx.y * 128;   // q rows
    const int n0  = blockIdx.x * 128;   // k rows
    const int tid = threadIdx.x;
    const int tx  = tid & 15;
    const int ty  = tid >> 4;
    const int lr  = tid >> 1;
    const int lc  = (tid & 1) * 4;

    const float* __restrict__ Q  = g_q  + (size_t)bh * kS * kDK;
    const float* __restrict__ KR = g_kr + (size_t)bh * kS * kDK;

    float acc[8][8];
#pragma unroll
    for (int i = 0; i < 8; ++i)
#pragma unroll
        for (int j = 0; j < 8; ++j) acc[i][j] = 0.f;

    for (int k0 = 0; k0 < kDK; k0 += 8) {
        float4 av = *reinterpret_cast<const float4*>(&Q [(m0 + lr) * kDK + k0 + lc]);
        float4 bv = *reinterpret_cast<const float4*>(&KR[(n0 + lr) * kDK + k0 + lc]);
        __syncthreads();
        As[lc + 0][lr] = av.x; As[lc + 1][lr] = av.y;
        As[lc + 2][lr] = av.z; As[lc + 3][lr] = av.w;
        Bs[lc + 0][lr] = bv.x; Bs[lc + 1][lr] = bv.y;
        Bs[lc + 2][lr] = bv.z; Bs[lc + 3][lr] = bv.w;
        __syncthreads();
#pragma unroll
        for (int kk = 0; kk < 8; ++kk) {
            float4 a0 = *reinterpret_cast<const float4*>(&As[kk][ty * 8]);
            float4 a1 = *reinterpret_cast<const float4*>(&As[kk][ty * 8 + 4]);
            float4 b0 = *reinterpret_cast<const float4*>(&Bs[kk][tx * 8]);
            float4 b1 = *reinterpret_cast<const float4*>(&Bs[kk][tx * 8 + 4]);
            float a[8] = {a0.x, a0.y, a0.z, a0.w, a1.x, a1.y, a1.z, a1.w};
            float b[8] = {b0.x, b0.y, b0.z, b0.w, b1.x, b1.y, b1.z, b1.w};
#pragma unroll
            for (int i = 0; i < 8; ++i)
#pragma unroll
                for (int j = 0; j < 8; ++j) acc[i][j] += a[i] * b[j];
        }
    }

    const int   b_    = bh >> 4;         // bh / kH
    const float scale = 0.125f;          // 1/sqrt(64)
#pragma unroll
    for (int i = 0; i < 8; ++i) {
        const int sq = m0 + ty * 8 + i;
        const int* __restrict__ mrow = &mask[((size_t)b_ * kS + sq) * kS];
        float* __restrict__ prow = &p[((size_t)bh * kS + sq) * kS];
#pragma unroll
        for (int j4 = 0; j4 < 8; j4 += 4) {
            const int sk = n0 + tx * 8 + j4;
            int4 mm = *reinterpret_cast<const int4*>(&mrow[sk]);
            float4 o;
            o.x = mm.x ? acc[i][j4 + 0] * scale : -1e9f;
            o.y = mm.y ? acc[i][j4 + 1] * scale : -1e9f;
            o.z = mm.z ? acc[i][j4 + 2] * scale : -1e9f;
            o.w = mm.w ? acc[i][j4 + 3] * scale : -1e9f;
            *reinterpret_cast<float4*>(&prow[sk]) = o;
        }
    }
}

// ---------------------------------------------------------------------------
// Per-row max + 1/sum(exp).  One block per row (2048 floats).
// ---------------------------------------------------------------------------
__global__ __launch_bounds__(256) void rowreduce_kernel(const float* __restrict__ p)
{
    __shared__ float red[256];
    const int row = blockIdx.x;
    const float4* __restrict__ pr = reinterpret_cast<const float4*>(p + (size_t)row * kS);
    const int tid = threadIdx.x;

    float4 v0 = pr[tid];
    float4 v1 = pr[tid + 256];
    float m = fmaxf(fmaxf(fmaxf(v0.x, v0.y), fmaxf(v0.z, v0.w)),
                    fmaxf(fmaxf(v1.x, v1.y), fmaxf(v1.z, v1.w)));
    red[tid] = m;
    __syncthreads();
    for (int s = 128; s > 0; s >>= 1) {
        if (tid < s) red[tid] = fmaxf(red[tid], red[tid + s]);
        __syncthreads();
    }
    const float rmax = red[0];
    __syncthreads();

    float sum = __expf(v0.x - rmax) + __expf(v0.y - rmax) +
                __expf(v0.z - rmax) + __expf(v0.w - rmax) +
                __expf(v1.x - rmax) + __expf(v1.y - rmax) +
                __expf(v1.z - rmax) + __expf(v1.w - rmax);
    red[tid] = sum;
    __syncthreads();
    for (int s = 128; s > 0; s >>= 1) {
        if (tid < s) red[tid] += red[tid + s];
        __syncthreads();
    }
    if (tid == 0) {
        g_rmax[row] = rmax;
        g_rinv[row] = 1.0f / red[0];
    }
}

// ---------------------------------------------------------------------------
// out = p @ v  (K = 2048), normalizing p on the fly and writing final p back.
// Tile 128 (rows) x 64 (full DK), BK=16, 256 threads, 8x4 per-thread microtile.
// grid (S/128, BH)
// ---------------------------------------------------------------------------
__global__ __launch_bounds__(256) void out_kernel(float* __restrict__ p,
                                                  float* __restrict__ out)
{
    __shared__ float As[16][128];
    __shared__ float Bs[16][64];
    __shared__ float s_max[128];
    __shared__ float s_inv[128];

    const int bh  = blockIdx.y;
    const int m0  = blockIdx.x * 128;
    const int tid = threadIdx.x;
    const int tx  = tid & 15;
    const int ty  = tid >> 4;

    if (tid < 128) {
        s_max[tid] = g_rmax[bh * kS + m0 + tid];
        s_inv[tid] = g_rinv[bh * kS + m0 + tid];
    }
    __syncthreads();

    float acc[8][4];
#pragma unroll
    for (int i = 0; i < 8; ++i)
#pragma unroll
        for (int j = 0; j < 4; ++j) acc[i][j] = 0.f;

    float* __restrict__ prow = p + (size_t)bh * kS * kS + (size_t)m0 * kS;
    const float* __restrict__ V = g_v + (size_t)bh * kS * kDK;

    const int r0 = tid >> 2;          // rows 0..63 (second load does +64)
    const int c0 = (tid & 3) * 4;     // k sub-offset 0..12
    const int vk = tid >> 4;          // 0..15
    const int vn = (tid & 15) * 4;    // 0..60

    for (int k0 = 0; k0 < kS; k0 += 16) {
        // load + normalize A tiles (raw masked scores -> probabilities)
        float4 x0 = *reinterpret_cast<const float4*>(&prow[(size_t)r0 * kS + k0 + c0]);
        float4 x1 = *reinterpret_cast<const float4*>(&prow[(size_t)(r0 + 64) * kS + k0 + c0]);
        const float mx0 = s_max[r0],      iv0 = s_inv[r0];
        const float mx1 = s_max[r0 + 64], iv1 = s_inv[r0 + 64];
        float4 n0v, n1v;
        n0v.x = __expf(x0.x - mx0) * iv0;  n0v.y = __expf(x0.y - mx0) * iv0;
        n0v.z = __expf(x0.z - mx0) * iv0;  n0v.w = __expf(x0.w - mx0) * iv0;
        n1v.x = __expf(x1.x - mx1) * iv1;  n1v.y = __expf(x1.y - mx1) * iv1;
        n1v.z = __expf(x1.z - mx1) * iv1;  n1v.w = __expf(x1.w - mx1) * iv1;

        float4 vb = *reinterpret_cast<const float4*>(&V[(k0 + vk) * kDK + vn]);

        __syncthreads();
        As[c0 + 0][r0]      = n0v.x; As[c0 + 1][r0]      = n0v.y;
        As[c0 + 2][r0]      = n0v.z; As[c0 + 3][r0]      = n0v.w;
        As[c0 + 0][r0 + 64] = n1v.x; As[c0 + 1][r0 + 64] = n1v.y;
        As[c0 + 2][r0 + 64] = n1v.z; As[c0 + 3][r0 + 64] = n1v.w;
        *reinterpret_cast<float4*>(&Bs[vk][vn]) = vb;

        // write final normalized probabilities back (each location touched once)
        *reinterpret_cast<float4*>(&prow[(size_t)r0 * kS + k0 + c0])        = n0v;
        *reinterpret_cast<float4*>(&prow[(size_t)(r0 + 64) * kS + k0 + c0]) = n1v;
        __syncthreads();

#pragma unroll
        for (int kk = 0; kk < 16; ++kk) {
            float4 a0 = *reinterpret_cast<const float4*>(&As[kk][ty * 8]);
            float4 a1 = *reinterpret_cast<const float4*>(&As[kk][ty * 8 + 4]);
            float4 bb = *reinterpret_cast<const float4*>(&Bs[kk][tx * 4]);
            float a[8]  = {a0.x, a0.y, a0.z, a0.w, a1.x, a1.y, a1.z, a1.w};
            float bj[4] = {bb.x, bb.y, bb.z, bb.w};
#pragma unroll
            for (int i = 0; i < 8; ++i)
#pragma unroll
                for (int j = 0; j < 4; ++j) acc[i][j] += a[i] * bj[j];
        }
    }

    float* __restrict__ orow = out + (size_t)bh * kS * kDK;
#pragma unroll
    for (int i = 0; i < 8; ++i) {
        float4 o = make_float4(acc[i][0], acc[i][1], acc[i][2], acc[i][3]);
        *reinterpret_cast<float4*>(&orow[(m0 + ty * 8 + i) * kDK + tx * 4]) = o;
    }
}

// ---------------------------------------------------------------------------
extern "C" void kernel_launch(void* const* d_in, const int* in_sizes, int n_in,
                              void* d_out, int out_size)
{
    (void)in_sizes; (void)n_in; (void)out_size;
    const float* query = (const float*)d_in[0];
    const float* key   = (const float*)d_in[1];
    const float* value = (const float*)d_in[2];
    const float* r     = (const float*)d_in[3];
    const int*   mask  = (const int*)  d_in[4];
    const float* Wq = (const float*)d_in[5];  const float* bq = (const float*)d_in[6];
    const float* Wk = (const float*)d_in[7];  const float* bk = (const float*)d_in[8];
    const float* Wv = (const float*)d_in[9];  const float* bv = (const float*)d_in[10];
    const float* Wr = (const float*)d_in[11]; const float* br = (const float*)d_in[12];

    float* out = (float*)d_out;                          // (B,H,S,DK)
    float* p   = out + (size_t)kBH * kS * kDK;           // (B,H,S,S)

    dim3 pgrid(kD / 128, kBS / 128);                     // (8, 32)
    proj_kernel<<<pgrid, 256>>>(query, Wq, bq, nullptr, nullptr, nullptr, 0);
    proj_kernel<<<pgrid, 256>>>(key,   Wk, bk, r, Wr, br, 1);   // kr = k_proj + r_proj
    proj_kernel<<<pgrid, 256>>>(value, Wv, bv, nullptr, nullptr, nullptr, 2);

    dim3 sgrid(kS / 128, kS / 128, kBH);                 // (16, 16, 32)
    scores_kernel<<<sgrid, 256>>>(mask, p);

    rowreduce_kernel<<<kNRows, 256>>>(p);

    dim3 ogrid(kS / 128, kBH);                           // (16, 32)
    out_kernel<<<ogrid, 256>>>(p, out);
}

// round 3
// speedup vs baseline: 1.1330x; 1.1330x over previous
#include <cuda_runtime.h>

// Problem constants
namespace {
constexpr int kB  = 2;
constexpr int kS  = 2048;
constexpr int kD  = 1024;
constexpr int kH  = 16;
constexpr int kDK = 64;
constexpr int kBH = kB * kH;        // 32
constexpr int kBS = kB * kS;        // 4096
constexpr int kNRows = kBH * kS;    // 65536 softmax rows
}

// Scratch (allocation-free rule: __device__ globals)
__device__ float g_q [kBH * kS * kDK];   // 16 MB
__device__ float g_kr[kBH * kS * kDK];   // 16 MB  (k_proj + r_proj)
__device__ float g_v [kBH * kS * kDK];   // 16 MB
__device__ float g_rinv[kNRows];         // 1 / sum(exp(row))

// ---------------------------------------------------------------------------
// Projection GEMM:  Y[m,e] = sum_d X1[m,d]*W1[e,d] (+ X2[m,d]*W2[e,d]) + bias
// written to head-major layout (b,h,s,dk).  dst_sel: 0=q, 1=kr, 2=v
// 128x128 tile, BK=8, 256 threads, 8x8 per-thread microtile.
// ---------------------------------------------------------------------------
__global__ __launch_bounds__(256) void proj_kernel(
    const float* __restrict__ X1, const float* __restrict__ W1, const float* __restrict__ bias1,
    const float* __restrict__ X2, const float* __restrict__ W2, const float* __restrict__ bias2,
    int dst_sel)
{
    __shared__ float As[8][128];
    __shared__ float Bs[8][128];

    const int m0  = blockIdx.y * 128;   // rows in (B*S)
    const int n0  = blockIdx.x * 128;   // cols in E=D
    const int tid = threadIdx.x;
    const int tx  = tid & 15;
    const int ty  = tid >> 4;
    const int lr  = tid >> 1;           // 0..127  (tile row for loads)
    const int lc  = (tid & 1) * 4;      // 0 or 4  (k sub-offset)

    float acc[8][8];
#pragma unroll
    for (int i = 0; i < 8; ++i)
#pragma unroll
        for (int j = 0; j < 8; ++j) acc[i][j] = 0.f;

    for (int pass = 0; pass < 2; ++pass) {
        const float* X = (pass == 0) ? X1 : X2;
        const float* W = (pass == 0) ? W1 : W2;
        if (X == nullptr) break;
        for (int k0 = 0; k0 < kD; k0 += 8) {
            float4 av = *reinterpret_cast<const float4*>(&X[(m0 + lr) * kD + k0 + lc]);
            float4 bv = *reinterpret_cast<const float4*>(&W[(n0 + lr) * kD + k0 + lc]);
            __syncthreads();
            As[lc + 0][lr] = av.x; As[lc + 1][lr] = av.y;
            As[lc + 2][lr] = av.z; As[lc + 3][lr] = av.w;
            Bs[lc + 0][lr] = bv.x; Bs[lc + 1][lr] = bv.y;
            Bs[lc + 2][lr] = bv.z; Bs[lc + 3][lr] = bv.w;
            __syncthreads();
#pragma unroll
            for (int kk = 0; kk < 8; ++kk) {
                float4 a0 = *reinterpret_cast<const float4*>(&As[kk][ty * 8]);
                float4 a1 = *reinterpret_cast<const float4*>(&As[kk][ty * 8 + 4]);
                float4 b0 = *reinterpret_cast<const float4*>(&Bs[kk][tx * 8]);
                float4 b1 = *reinterpret_cast<const float4*>(&Bs[kk][tx * 8 + 4]);
                float a[8] = {a0.x, a0.y, a0.z, a0.w, a1.x, a1.y, a1.z, a1.w};
                float b[8] = {b0.x, b0.y, b0.z, b0.w, b1.x, b1.y, b1.z, b1.w};
#pragma unroll
                for (int i = 0; i < 8; ++i)
#pragma unroll
                    for (int j = 0; j < 8; ++j) acc[i][j] += a[i] * b[j];
            }
        }
    }

    float* __restrict__ dst = (dst_sel == 0) ? g_q : (dst_sel == 1) ? g_kr : g_v;

    float bsum[8];
#pragma unroll
    for (int j = 0; j < 8; ++j) {
        const int e = n0 + tx * 8 + j;
        bsum[j] = bias1[e] + (X2 ? bias2[e] : 0.f);
    }

#pragma unroll
    for (int i = 0; i < 8; ++i) {
        const int m    = m0 + ty * 8 + i;
        const int bidx = m >> 11;          // m / kS
        const int s    = m & (kS - 1);
#pragma unroll
        for (int j = 0; j < 8; ++j) {
            const int e  = n0 + tx * 8 + j;
            const int h  = e >> 6;         // e / kDK
            const int dk = e & 63;
            dst[((bidx * kH + h) * kS + s) * kDK + dk] = acc[i][j] + bsum[j];
        }
    }
}

// ---------------------------------------------------------------------------
// Fused scores + softmax numerator + row sums (max-free softmax).
//   e = mask ? exp(q@kr^T * scale) : 0   written to p region (raw numerators)
//   g_rinv[row] = 1 / sum_k e
// Q strip (128 x 64) resident in smem; KR streamed in 8x128 chunks.
// grid (S/128, BH), 256 threads, 8x8 microtile, 2 blocks/SM.
// ---------------------------------------------------------------------------
__global__ __launch_bounds__(256, 2) void scores_sum_kernel(const int* __restrict__ mask,
                                                            float* __restrict__ p)
{
    __shared__ float Qs[64][132];   // padded: conflict-light stores, aligned rows
    __shared__ float Bs[8][128];

    const int bh  = blockIdx.y;
    const int m0  = blockIdx.x * 128;
    const int tid = threadIdx.x;
    const int tx  = tid & 15;
    const int ty  = tid >> 4;
    const int lr  = tid >> 1;
    const int lc  = (tid & 1) * 4;

    const float* __restrict__ Q  = g_q  + (size_t)bh * kS * kDK;
    const float* __restrict__ KR = g_kr + (size_t)bh * kS * kDK;

    // Load Q strip: rows m0..m0+127, all 64 k values, stored k-major.
    for (int i = tid; i < 128 * 16; i += 256) {
        const int row = i >> 4;
        const int kq  = (i & 15) * 4;
        float4 v = *reinterpret_cast<const float4*>(&Q[(m0 + row) * kDK + kq]);
        Qs[kq + 0][row] = v.x; Qs[kq + 1][row] = v.y;
        Qs[kq + 2][row] = v.z; Qs[kq + 3][row] = v.w;
    }

    float rowsum[8];
#pragma unroll
    for (int i = 0; i < 8; ++i) rowsum[i] = 0.f;

    const int   b_    = bh >> 4;         // batch index
    const float scale = 0.125f;          // 1/sqrt(64)

    for (int n0 = 0; n0 < kS; n0 += 128) {
        float acc[8][8];
#pragma unroll
        for (int i = 0; i < 8; ++i)
#pragma unroll
            for (int j = 0; j < 8; ++j) acc[i][j] = 0.f;

        for (int k0 = 0; k0 < kDK; k0 += 8) {
            float4 bv = *reinterpret_cast<const float4*>(&KR[(n0 + lr) * kDK + k0 + lc]);
            __syncthreads();
            Bs[lc + 0][lr] = bv.x; Bs[lc + 1][lr] = bv.y;
            Bs[lc + 2][lr] = bv.z; Bs[lc + 3][lr] = bv.w;
            __syncthreads();
#pragma unroll
            for (int kk = 0; kk < 8; ++kk) {
                float4 a0 = *reinterpret_cast<const float4*>(&Qs[k0 + kk][ty * 8]);
                float4 a1 = *reinterpret_cast<const float4*>(&Qs[k0 + kk][ty * 8 + 4]);
                float4 b0 = *reinterpret_cast<const float4*>(&Bs[kk][tx * 8]);
                float4 b1 = *reinterpret_cast<const float4*>(&Bs[kk][tx * 8 + 4]);
                float a[8] = {a0.x, a0.y, a0.z, a0.w, a1.x, a1.y, a1.z, a1.w};
                float b[8] = {b0.x, b0.y, b0.z, b0.w, b1.x, b1.y, b1.z, b1.w};
#pragma unroll
                for (int i = 0; i < 8; ++i)
#pragma unroll
                    for (int j = 0; j < 8; ++j) acc[i][j] += a[i] * b[j];
            }
        }

        // epilogue: mask -> exp -> store numerators -> accumulate row sums
#pragma unroll
        for (int i = 0; i < 8; ++i) {
            const int sq = m0 + ty * 8 + i;
            const int* __restrict__ mrow = &mask[((size_t)b_ * kS + sq) * kS];
            float* __restrict__ prow = &p[((size_t)bh * kS + sq) * kS];
#pragma unroll
            for (int j4 = 0; j4 < 8; j4 += 4) {
                const int sk = n0 + tx * 8 + j4;
                int4 mm = *reinterpret_cast<const int4*>(&mrow[sk]);
                float4 e;
                e.x = mm.x ? __expf(acc[i][j4 + 0] * scale) : 0.f;
                e.y = mm.y ? __expf(acc[i][j4 + 1] * scale) : 0.f;
                e.z = mm.z ? __expf(acc[i][j4 + 2] * scale) : 0.f;
                e.w = mm.w ? __expf(acc[i][j4 + 3] * scale) : 0.f;
                *reinterpret_cast<float4*>(&prow[sk]) = e;
                rowsum[i] += (e.x + e.y) + (e.z + e.w);
            }
        }
    }

    // reduce row sums across the 16 tx lanes (within half-warp), write 1/sum
#pragma unroll
    for (int i = 0; i < 8; ++i) {
        float s = rowsum[i];
        s += __shfl_xor_sync(0xffffffffu, s, 1);
        s += __shfl_xor_sync(0xffffffffu, s, 2);
        s += __shfl_xor_sync(0xffffffffu, s, 4);
        s += __shfl_xor_sync(0xffffffffu, s, 8);
        if (tx == 0) g_rinv[bh * kS + m0 + ty * 8 + i] = 1.0f / s;
    }
}

// ---------------------------------------------------------------------------
// out = p @ v  (K = 2048): reads numerators e, normalizes (e * rinv),
// writes final p back, accumulates p@v.
// Tile 128 (rows) x 64 (full DK), BK=16, 256 threads, 8x4 per-thread microtile.
// grid (S/128, BH)
// ---------------------------------------------------------------------------
__global__ __launch_bounds__(256, 2) void out_kernel(float* __restrict__ p,
                                                     float* __restrict__ out)
{
    __shared__ float As[16][128];
    __shared__ float Bs[16][64];
    __shared__ float s_inv[128];

    const int bh  = blockIdx.y;
    const int m0  = blockIdx.x * 128;
    const int tid = threadIdx.x;
    const int tx  = tid & 15;
    const int ty  = tid >> 4;

    if (tid < 128) {
        s_inv[tid] = g_rinv[bh * kS + m0 + tid];
    }
    __syncthreads();

    float acc[8][4];
#pragma unroll
    for (int i = 0; i < 8; ++i)
#pragma unroll
        for (int j = 0; j < 4; ++j) acc[i][j] = 0.f;

    float* __restrict__ prow = p + (size_t)bh * kS * kS + (size_t)m0 * kS;
    const float* __restrict__ V = g_v + (size_t)bh * kS * kDK;

    const int r0 = tid >> 2;          // rows 0..63 (second load does +64)
    const int c0 = (tid & 3) * 4;     // k sub-offset 0..12
    const int vk = tid >> 4;          // 0..15
    const int vn = (tid & 15) * 4;    // 0..60

    const float iv0 = s_inv[r0];
    const float iv1 = s_inv[r0 + 64];

    for (int k0 = 0; k0 < kS; k0 += 16) {
        // load numerators, normalize
        float4 x0 = *reinterpret_cast<const float4*>(&prow[(size_t)r0 * kS + k0 + c0]);
        float4 x1 = *reinterpret_cast<const float4*>(&prow[(size_t)(r0 + 64) * kS + k0 + c0]);
        float4 n0v, n1v;
        n0v.x = x0.x * iv0;  n0v.y = x0.y * iv0;
        n0v.z = x0.z * iv0;  n0v.w = x0.w * iv0;
        n1v.x = x1.x * iv1;  n1v.y = x1.y * iv1;
        n1v.z = x1.z * iv1;  n1v.w = x1.w * iv1;

        float4 vb = *reinterpret_cast<const float4*>(&V[(k0 + vk) * kDK + vn]);

        __syncthreads();
        As[c0 + 0][r0]      = n0v.x; As[c0 + 1][r0]      = n0v.y;
        As[c0 + 2][r0]      = n0v.z; As[c0 + 3][r0]      = n0v.w;
        As[c0 + 0][r0 + 64] = n1v.x; As[c0 + 1][r0 + 64] = n1v.y;
        As[c0 + 2][r0 + 64] = n1v.z; As[c0 + 3][r0 + 64] = n1v.w;
        *reinterpret_cast<float4*>(&Bs[vk][vn]) = vb;

        // write final normalized probabilities back (each location touched once)
        *reinterpret_cast<float4*>(&prow[(size_t)r0 * kS + k0 + c0])        = n0v;
        *reinterpret_cast<float4*>(&prow[(size_t)(r0 + 64) * kS + k0 + c0]) = n1v;
        __syncthreads();

#pragma unroll
        for (int kk = 0; kk < 16; ++kk) {
            float4 a0 = *reinterpret_cast<const float4*>(&As[kk][ty * 8]);
            float4 a1 = *reinterpret_cast<const float4*>(&As[kk][ty * 8 + 4]);
            float4 bb = *reinterpret_cast<const float4*>(&Bs[kk][tx * 4]);
            float a[8]  = {a0.x, a0.y, a0.z, a0.w, a1.x, a1.y, a1.z, a1.w};
            float bj[4] = {bb.x, bb.y, bb.z, bb.w};
#pragma unroll
            for (int i = 0; i < 8; ++i)
#pragma unroll
                for (int j = 0; j < 4; ++j) acc[i][j] += a[i] * bj[j];
        }
    }

    float* __restrict__ orow = out + (size_t)bh * kS * kDK;
#pragma unroll
    for (int i = 0; i < 8; ++i) {
        float4 o = make_float4(acc[i][0], acc[i][1], acc[i][2], acc[i][3]);
        *reinterpret_cast<float4*>(&orow[(m0 + ty * 8 + i) * kDK + tx * 4]) = o;
    }
}

// ---------------------------------------------------------------------------
extern "C" void kernel_launch(void* const* d_in, const int* in_sizes, int n_in,
                              void* d_out, int out_size)
{
    (void)in_sizes; (void)n_in; (void)out_size;
    const float* query = (const float*)d_in[0];
    const float* key   = (const float*)d_in[1];
    const float* value = (const float*)d_in[2];
    const float* r     = (const float*)d_in[3];
    const int*   mask  = (const int*)  d_in[4];
    const float* Wq = (const float*)d_in[5];  const float* bq = (const float*)d_in[6];
    const float* Wk = (const float*)d_in[7];  const float* bk = (const float*)d_in[8];
    const float* Wv = (const float*)d_in[9];  const float* bv = (const float*)d_in[10];
    const float* Wr = (const float*)d_in[11]; const float* br = (const float*)d_in[12];

    float* out = (float*)d_out;                          // (B,H,S,DK)
    float* p   = out + (size_t)kBH * kS * kDK;           // (B,H,S,S)

    dim3 pgrid(kD / 128, kBS / 128);                     // (8, 32)
    proj_kernel<<<pgrid, 256>>>(query, Wq, bq, nullptr, nullptr, nullptr, 0);
    proj_kernel<<<pgrid, 256>>>(key,   Wk, bk, r, Wr, br, 1);   // kr = k_proj + r_proj
    proj_kernel<<<pgrid, 256>>>(value, Wv, bv, nullptr, nullptr, nullptr, 2);

    dim3 sgrid(kS / 128, kBH);                           // (16, 32)
    scores_sum_kernel<<<sgrid, 256>>>(mask, p);

    dim3 ogrid(kS / 128, kBH);                           // (16, 32)
    out_kernel<<<ogrid, 256>>>(p, out);
}

// round 6
// speedup vs baseline: 1.2149x; 1.0723x over previous
#include <cuda_runtime.h>
#include <cstdint>

// ===========================================================================
// Problem constants
// ===========================================================================
namespace {
constexpr int kB  = 2;
constexpr int kS  = 2048;
constexpr int kD  = 1024;
constexpr int kH  = 16;
constexpr int kDK = 64;
constexpr int kBH = kB * kH;        // 32
constexpr int kBS = kB * kS;        // 4096
constexpr int kNRows = kBH * kS;    // 65536
}

// Scratch (allocation-free rule: __device__ globals)
__device__ float g_q [kBH * kS * kDK];   // 16 MB
__device__ float g_kr[kBH * kS * kDK];   // 16 MB (k_proj + r_proj)
__device__ float g_v [kBH * kS * kDK];   // 16 MB
__device__ float g_rinv[kNRows];

// ===========================================================================
// tf32 helpers (arch-neutral PTX, valid on sm_100 target)
// ===========================================================================
__device__ __forceinline__ void split_tf32(float x, uint32_t& hi, uint32_t& lo) {
    uint32_t h;
    asm("cvt.rna.tf32.f32 %0, %1;" : "=r"(h) : "f"(x));
    float lf = x - __uint_as_float(h);
    uint32_t l;
    asm("cvt.rna.tf32.f32 %0, %1;" : "=r"(l) : "f"(lf));
    hi = h; lo = l;
}

// D += A(tf32) * B(tf32); m16n8k8, A row-major, B col-major.
__device__ __forceinline__ void mma_m16n8k8_tf32(float* d, const uint32_t* a,
                                                 const uint32_t* b) {
    asm volatile(
        "mma.sync.aligned.m16n8k8.row.col.f32.tf32.tf32.f32 "
        "{%0,%1,%2,%3}, {%4,%5,%6,%7}, {%8,%9}, {%0,%1,%2,%3};"
        : "+f"(d[0]), "+f"(d[1]), "+f"(d[2]), "+f"(d[3])
        : "r"(a[0]), "r"(a[1]), "r"(a[2]), "r"(a[3]), "r"(b[0]), "r"(b[1]));
}

// ===========================================================================
// Projection GEMM via mma.sync tf32x3.
//   D[m,e] = sum_d X1[m,d]*W1[e,d]  (+ X2[m,d]*W2[e,d] if ns==64) + bias
// 128x128 CTA tile, BK=32, 8 warps as 2(m) x 4(n); warp tile 64x32
// = 4 m16-tiles x 4 n8-tiles. tf32x3: hi*hi + hi*lo + lo*hi.
// Output scattered to head-major (b,h,s,dk) in g_q / g_kr / g_v.
// grid (D/128, BS/128), 256 threads.
// ===========================================================================
__global__ __launch_bounds__(256) void proj_mma_kernel(
    const float* __restrict__ X1, const float* __restrict__ W1, const float* __restrict__ b1,
    const float* __restrict__ X2, const float* __restrict__ W2, const float* __restrict__ b2,
    int dst_sel, int ns)
{
    __shared__ float As[32][133];   // [k][m], pad 133: conflict-free store & frag load
    __shared__ float Bs[32][133];   // [k][n]

    const int tid   = threadIdx.x;
    const int wid   = tid >> 5;
    const int lane  = tid & 31;
    const int gid   = lane >> 2;          // 0..7
    const int tid4  = lane & 3;           // 0..3
    const int wm    = (wid >> 2) * 64;    // warp m-offset: 0 / 64
    const int wn    = (wid & 3) * 32;     // warp n-offset: 0/32/64/96
    const int m0    = blockIdx.y * 128;
    const int n0    = blockIdx.x * 128;

    float acc[4][4][4];                   // [mtile][ntile][frag]
#pragma unroll
    for (int mt = 0; mt < 4; ++mt)
#pragma unroll
        for (int nt = 0; nt < 4; ++nt)
#pragma unroll
            for (int f = 0; f < 4; ++f) acc[mt][nt][f] = 0.f;

    for (int s = 0; s < ns; ++s) {
        const float* __restrict__ X = (s < 32) ? X1 : X2;
        const float* __restrict__ W = (s < 32) ? W1 : W2;
        const int k0 = (s & 31) * 32;

        // ---- stage load: global -> regs ----
        float4 xa[4], wb[4];
#pragma unroll
        for (int i = 0; i < 4; ++i) {
            const int idx = tid + 256 * i;       // 0..1023
            const int row = idx >> 3;            // 0..127
            const int c4  = (idx & 7) * 4;       // 0..28
            xa[i] = *reinterpret_cast<const float4*>(&X[(size_t)(m0 + row) * kD + k0 + c4]);
            wb[i] = *reinterpret_cast<const float4*>(&W[(size_t)(n0 + row) * kD + k0 + c4]);
        }
        __syncthreads();                          // smem free (prev compute done)
#pragma unroll
        for (int i = 0; i < 4; ++i) {
            const int idx = tid + 256 * i;
            const int row = idx >> 3;
            const int c4  = (idx & 7) * 4;
            As[c4 + 0][row] = xa[i].x; As[c4 + 1][row] = xa[i].y;
            As[c4 + 2][row] = xa[i].z; As[c4 + 3][row] = xa[i].w;
            Bs[c4 + 0][row] = wb[i].x; Bs[c4 + 1][row] = wb[i].y;
            Bs[c4 + 2][row] = wb[i].z; Bs[c4 + 3][row] = wb[i].w;
        }
        __syncthreads();

        // ---- compute: 4 k8-steps ----
#pragma unroll
        for (int kk = 0; kk < 4; ++kk) {
            const int kb = kk * 8;

            // B fragments (4 n8-tiles), split hi/lo
            uint32_t bh[4][2], bl[4][2];
#pragma unroll
            for (int nt = 0; nt < 4; ++nt) {
                const int n = wn + nt * 8 + gid;
                split_tf32(Bs[kb + tid4    ][n], bh[nt][0], bl[nt][0]);
                split_tf32(Bs[kb + tid4 + 4][n], bh[nt][1], bl[nt][1]);
            }

#pragma unroll
            for (int mt = 0; mt < 4; ++mt) {
                const int m = wm + mt * 16 + gid;
                uint32_t ah[4], al[4];
                split_tf32(As[kb + tid4    ][m    ], ah[0], al[0]);
                split_tf32(As[kb + tid4    ][m + 8], ah[1], al[1]);
                split_tf32(As[kb + tid4 + 4][m    ], ah[2], al[2]);
                split_tf32(As[kb + tid4 + 4][m + 8], ah[3], al[3]);
#pragma unroll
                for (int nt = 0; nt < 4; ++nt) {
                    mma_m16n8k8_tf32(acc[mt][nt], ah, bh[nt]);
                    mma_m16n8k8_tf32(acc[mt][nt], ah, bl[nt]);
                    mma_m16n8k8_tf32(acc[mt][nt], al, bh[nt]);
                }
            }
        }
    }

    // ---- epilogue: bias add + head-major scatter ----
    // frag -> C[row][col]: c0,c1 = C[gid][2*tid4 + 0/1], c2,c3 = C[gid+8][...]
    float* __restrict__ dst = (dst_sel == 0) ? g_q : (dst_sel == 1) ? g_kr : g_v;
#pragma unroll
    for (int nt = 0; nt < 4; ++nt) {
        const int e = n0 + wn + nt * 8 + 2 * tid4;
        const int h   = e >> 6;
        const int dk  = e & 63;
        float2 bb;
        bb.x = b1[e];     bb.y = b1[e + 1];
        if (X2) { bb.x += b2[e]; bb.y += b2[e + 1]; }
#pragma unroll
        for (int mt = 0; mt < 4; ++mt) {
#pragma unroll
            for (int half = 0; half < 2; ++half) {
                const int gm   = m0 + wm + mt * 16 + gid + half * 8;
                const int bidx = gm >> 11;
                const int srow = gm & (kS - 1);
                float2 o;
                o.x = acc[mt][nt][half * 2 + 0] + bb.x;
                o.y = acc[mt][nt][half * 2 + 1] + bb.y;
                *reinterpret_cast<float2*>(
                    &dst[(((size_t)bidx * kH + h) * kS + srow) * kDK + dk]) = o;
            }
        }
    }
}

// ===========================================================================
// Fused scores + softmax numerator + row sums (max-free softmax). Unchanged.
// ===========================================================================
__global__ __launch_bounds__(256, 2) void scores_sum_kernel(const int* __restrict__ mask,
                                                            float* __restrict__ p)
{
    __shared__ float Qs[64][132];
    __shared__ float Bs[8][128];

    const int bh  = blockIdx.y;
    const int m0  = blockIdx.x * 128;
    const int tid = threadIdx.x;
    const int tx  = tid & 15;
    const int ty  = tid >> 4;
    const int lr  = tid >> 1;
    const int lc  = (tid & 1) * 4;

    const float* __restrict__ Q  = g_q  + (size_t)bh * kS * kDK;
    const float* __restrict__ KR = g_kr + (size_t)bh * kS * kDK;

    for (int i = tid; i < 128 * 16; i += 256) {
        const int row = i >> 4;
        const int kq  = (i & 15) * 4;
        float4 v = *reinterpret_cast<const float4*>(&Q[(m0 + row) * kDK + kq]);
        Qs[kq + 0][row] = v.x; Qs[kq + 1][row] = v.y;
        Qs[kq + 2][row] = v.z; Qs[kq + 3][row] = v.w;
    }

    float rowsum[8];
#pragma unroll
    for (int i = 0; i < 8; ++i) rowsum[i] = 0.f;

    const int   b_    = bh >> 4;
    const float scale = 0.125f;

    for (int n0 = 0; n0 < kS; n0 += 128) {
        float acc[8][8];
#pragma unroll
        for (int i = 0; i < 8; ++i)
#pragma unroll
            for (int j = 0; j < 8; ++j) acc[i][j] = 0.f;

        for (int k0 = 0; k0 < kDK; k0 += 8) {
            float4 bv = *reinterpret_cast<const float4*>(&KR[(n0 + lr) * kDK + k0 + lc]);
            __syncthreads();
            Bs[lc + 0][lr] = bv.x; Bs[lc + 1][lr] = bv.y;
            Bs[lc + 2][lr] = bv.z; Bs[lc + 3][lr] = bv.w;
            __syncthreads();
#pragma unroll
            for (int kk = 0; kk < 8; ++kk) {
                float4 a0 = *reinterpret_cast<const float4*>(&Qs[k0 + kk][ty * 8]);
                float4 a1 = *reinterpret_cast<const float4*>(&Qs[k0 + kk][ty * 8 + 4]);
                float4 b0 = *reinterpret_cast<const float4*>(&Bs[kk][tx * 8]);
                float4 b1 = *reinterpret_cast<const float4*>(&Bs[kk][tx * 8 + 4]);
                float a[8] = {a0.x, a0.y, a0.z, a0.w, a1.x, a1.y, a1.z, a1.w};
                float b[8] = {b0.x, b0.y, b0.z, b0.w, b1.x, b1.y, b1.z, b1.w};
#pragma unroll
                for (int i = 0; i < 8; ++i)
#pragma unroll
                    for (int j = 0; j < 8; ++j) acc[i][j] += a[i] * b[j];
            }
        }

#pragma unroll
        for (int i = 0; i < 8; ++i) {
            const int sq = m0 + ty * 8 + i;
            const int* __restrict__ mrow = &mask[((size_t)b_ * kS + sq) * kS];
            float* __restrict__ prow = &p[((size_t)bh * kS + sq) * kS];
#pragma unroll
            for (int j4 = 0; j4 < 8; j4 += 4) {
                const int sk = n0 + tx * 8 + j4;
                int4 mm = *reinterpret_cast<const int4*>(&mrow[sk]);
                float4 e;
                e.x = mm.x ? __expf(acc[i][j4 + 0] * scale) : 0.f;
                e.y = mm.y ? __expf(acc[i][j4 + 1] * scale) : 0.f;
                e.z = mm.z ? __expf(acc[i][j4 + 2] * scale) : 0.f;
                e.w = mm.w ? __expf(acc[i][j4 + 3] * scale) : 0.f;
                *reinterpret_cast<float4*>(&prow[sk]) = e;
                rowsum[i] += (e.x + e.y) + (e.z + e.w);
            }
        }
    }

#pragma unroll
    for (int i = 0; i < 8; ++i) {
        float s = rowsum[i];
        s += __shfl_xor_sync(0xffffffffu, s, 1);
        s += __shfl_xor_sync(0xffffffffu, s, 2);
        s += __shfl_xor_sync(0xffffffffu, s, 4);
        s += __shfl_xor_sync(0xffffffffu, s, 8);
        if (tx == 0) g_rinv[bh * kS + m0 + ty * 8 + i] = 1.0f / s;
    }
}

// ===========================================================================
// out = p @ v with on-the-fly normalization; writes final p back. Unchanged.
// ===========================================================================
__global__ __launch_bounds__(256, 2) void out_kernel(float* __restrict__ p,
                                                     float* __restrict__ out)
{
    __shared__ float As[16][128];
    __shared__ float Bs[16][64];
    __shared__ float s_inv[128];

    const int bh  = blockIdx.y;
    const int m0  = blockIdx.x * 128;
    const int tid = threadIdx.x;
    const int tx  = tid & 15;
    const int ty  = tid >> 4;

    if (tid < 128) {
        s_inv[tid] = g_rinv[bh * kS + m0 + tid];
    }
    __syncthreads();

    float acc[8][4];
#pragma unroll
    for (int i = 0; i < 8; ++i)
#pragma unroll
        for (int j = 0; j < 4; ++j) acc[i][j] = 0.f;

    float* __restrict__ prow = p + (size_t)bh * kS * kS + (size_t)m0 * kS;
    const float* __restrict__ V = g_v + (size_t)bh * kS * kDK;

    const int r0 = tid >> 2;
    const int c0 = (tid & 3) * 4;
    const int vk = tid >> 4;
    const int vn = (tid & 15) * 4;

    const float iv0 = s_inv[r0];
    const float iv1 = s_inv[r0 + 64];

    for (int k0 = 0; k0 < kS; k0 += 16) {
        float4 x0 = *reinterpret_cast<const float4*>(&prow[(size_t)r0 * kS + k0 + c0]);
        float4 x1 = *reinterpret_cast<const float4*>(&prow[(size_t)(r0 + 64) * kS + k0 + c0]);
        float4 n0v, n1v;
        n0v.x = x0.x * iv0;  n0v.y = x0.y * iv0;
        n0v.z = x0.z * iv0;  n0v.w = x0.w * iv0;
        n1v.x = x1.x * iv1;  n1v.y = x1.y * iv1;
        n1v.z = x1.z * iv1;  n1v.w = x1.w * iv1;

        float4 vb = *reinterpret_cast<const float4*>(&V[(k0 + vk) * kDK + vn]);

        __syncthreads();
        As[c0 + 0][r0]      = n0v.x; As[c0 + 1][r0]      = n0v.y;
        As[c0 + 2][r0]      = n0v.z; As[c0 + 3][r0]      = n0v.w;
        As[c0 + 0][r0 + 64] = n1v.x; As[c0 + 1][r0 + 64] = n1v.y;
        As[c0 + 2][r0 + 64] = n1v.z; As[c0 + 3][r0 + 64] = n1v.w;
        *reinterpret_cast<float4*>(&Bs[vk][vn]) = vb;

        *reinterpret_cast<float4*>(&prow[(size_t)r0 * kS + k0 + c0])        = n0v;
        *reinterpret_cast<float4*>(&prow[(size_t)(r0 + 64) * kS + k0 + c0]) = n1v;
        __syncthreads();

#pragma unroll
        for (int kk = 0; kk < 16; ++kk) {
            float4 a0 = *reinterpret_cast<const float4*>(&As[kk][ty * 8]);
            float4 a1 = *reinterpret_cast<const float4*>(&As[kk][ty * 8 + 4]);
            float4 bb = *reinterpret_cast<const float4*>(&Bs[kk][tx * 4]);
            float a[8]  = {a0.x, a0.y, a0.z, a0.w, a1.x, a1.y, a1.z, a1.w};
            float bj[4] = {bb.x, bb.y, bb.z, bb.w};
#pragma unroll
            for (int i = 0; i < 8; ++i)
#pragma unroll
                for (int j = 0; j < 4; ++j) acc[i][j] += a[i] * bj[j];
        }
    }

    float* __restrict__ orow = out + (size_t)bh * kS * kDK;
#pragma unroll
    for (int i = 0; i < 8; ++i) {
        float4 o = make_float4(acc[i][0], acc[i][1], acc[i][2], acc[i][3]);
        *reinterpret_cast<float4*>(&orow[(m0 + ty * 8 + i) * kDK + tx * 4]) = o;
    }
}

// ===========================================================================
extern "C" void kernel_launch(void* const* d_in, const int* in_sizes, int n_in,
                              void* d_out, int out_size)
{
    (void)in_sizes; (void)n_in; (void)out_size;
    const float* query = (const float*)d_in[0];
    const float* key   = (const float*)d_in[1];
    const float* value = (const float*)d_in[2];
    const float* r     = (const float*)d_in[3];
    const int*   mask  = (const int*)  d_in[4];
    const float* Wq = (const float*)d_in[5];  const float* bq = (const float*)d_in[6];
    const float* Wk = (const float*)d_in[7];  const float* bk = (const float*)d_in[8];
    const float* Wv = (const float*)d_in[9];  const float* bv = (const float*)d_in[10];
    const float* Wr = (const float*)d_in[11]; const float* br = (const float*)d_in[12];

    float* out = (float*)d_out;                          // (B,H,S,DK)
    float* p   = out + (size_t)kBH * kS * kDK;           // (B,H,S,S)

    dim3 pgrid(kD / 128, kBS / 128);                     // (8, 32)
    proj_mma_kernel<<<pgrid, 256>>>(query, Wq, bq, nullptr, nullptr, nullptr, 0, 32);
    proj_mma_kernel<<<pgrid, 256>>>(key,   Wk, bk, r, Wr, br, 1, 64);  // kr
    proj_mma_kernel<<<pgrid, 256>>>(value, Wv, bv, nullptr, nullptr, nullptr, 2, 32);

    dim3 sgrid(kS / 128, kBH);                           // (16, 32)
    scores_sum_kernel<<<sgrid, 256>>>(mask, p);

    dim3 ogrid(kS / 128, kBH);                           // (16, 32)
    out_kernel<<<ogrid, 256>>>(p, out);
}